// round 5
// baseline (speedup 1.0000x reference)
#include <cuda_runtime.h>
#include <cuda_fp16.h>
#include <math.h>
#include <stdint.h>

// ---------------------------------------------------------------------------
// NetGIN round 5: fp16 CSR gather with HADD2 accumulation (flush every <=8
// edges), fused scan+proj, per-call state zeroing moved into final_kernel.
// Launch order: hist(1), scan+proj(2), fill(3), 5x layer(4..8), final(9).
// Invariant: rowptr/desc/sAcc are zero on entry (module-load init + final
// kernel re-zeroes them each call -> identical work every call).
// ---------------------------------------------------------------------------

#define NMAX     500000
#define EMAX     16000000
#define STRIDE_H 16          // halves per row (32 B = 1 L2 sector)
#define DIM      10
#define GMAX     8192
#define TILE     1024
#define NDESC    1024

__device__ __align__(32) __half g_zA[NMAX * STRIDE_H];
__device__ __align__(32) __half g_zB[NMAX * STRIDE_H];
__device__ __align__(16) int g_srcSorted[EMAX];
__device__ int   g_rowptr[NMAX + 1];
__device__ int   g_cursor[NMAX];
__device__ unsigned long long g_desc[NDESC];
__device__ float g_s[GMAX];

// ---------------- fp16 helpers ----------------

__device__ __forceinline__ void store_row_h(__half* __restrict__ z, int i, const float v[DIM]) {
    __half2 p0 = __floats2half2_rn(v[0], v[1]);
    __half2 p1 = __floats2half2_rn(v[2], v[3]);
    __half2 p2 = __floats2half2_rn(v[4], v[5]);
    __half2 p3 = __floats2half2_rn(v[6], v[7]);
    __half2 p4 = __floats2half2_rn(v[8], v[9]);
    uint4 w;
    w.x = *reinterpret_cast<uint32_t*>(&p0);
    w.y = *reinterpret_cast<uint32_t*>(&p1);
    w.z = *reinterpret_cast<uint32_t*>(&p2);
    w.w = *reinterpret_cast<uint32_t*>(&p3);
    __half* zp = z + (size_t)i * STRIDE_H;
    *reinterpret_cast<uint4*>(zp) = w;
    *(reinterpret_cast<uint32_t*>(zp) + 4) = *reinterpret_cast<uint32_t*>(&p4);
}

// accumulate one row into packed half2 accumulators (5 HADD2, 2 LDG)
__device__ __forceinline__ void add_row_h16(const __half* __restrict__ z, int s, __half2 hacc[5]) {
    const __half* zs = z + (size_t)s * STRIDE_H;
    uint4 a = __ldg(reinterpret_cast<const uint4*>(zs));
    uint32_t b = __ldg(reinterpret_cast<const uint32_t*>(zs) + 4);
    hacc[0] = __hadd2(hacc[0], *reinterpret_cast<__half2*>(&a.x));
    hacc[1] = __hadd2(hacc[1], *reinterpret_cast<__half2*>(&a.y));
    hacc[2] = __hadd2(hacc[2], *reinterpret_cast<__half2*>(&a.z));
    hacc[3] = __hadd2(hacc[3], *reinterpret_cast<__half2*>(&a.w));
    hacc[4] = __hadd2(hacc[4], *reinterpret_cast<__half2*>(&b));
}

__device__ __forceinline__ void flush_h16(float acc[DIM], __half2 hacc[5]) {
    __half2 hz = __floats2half2_rn(0.0f, 0.0f);
#pragma unroll
    for (int j = 0; j < 5; j++) {
        float2 f = __half22float2(hacc[j]);
        acc[2 * j]     += f.x;
        acc[2 * j + 1] += f.y;
        hacc[j] = hz;
    }
}

// ---------------- K1: histogram of dst (4 edges/thread) ----------------

__global__ void hist_kernel(const int* __restrict__ dst, int* __restrict__ rowptr, int E) {
    int e = (blockIdx.x * blockDim.x + threadIdx.x) * 4;
    if (e + 3 < E) {
        int4 d = __ldg(reinterpret_cast<const int4*>(dst + e));
        atomicAdd(&rowptr[d.x + 1], 1);
        atomicAdd(&rowptr[d.y + 1], 1);
        atomicAdd(&rowptr[d.z + 1], 1);
        atomicAdd(&rowptr[d.w + 1], 1);
    } else {
        for (int k = e; k < E; k++) atomicAdd(&rowptr[__ldg(&dst[k]) + 1], 1);
    }
}

// ---------------- K2: single-pass lookback scan + layer-1 projection --------

__global__ void __launch_bounds__(TILE)
scanproj_kernel(int* __restrict__ rowptr, int n,
                unsigned long long* __restrict__ desc,
                int* __restrict__ cursor,
                const float* __restrict__ h,
                const float* __restrict__ W1,
                __half* __restrict__ z, int N) {
    __shared__ int sh[TILE];
    __shared__ int s_excl;
    int part = blockIdx.x;
    int gid = part * TILE + threadIdx.x;

    int v = (gid < n) ? rowptr[gid] : 0;
    sh[threadIdx.x] = v;
    __syncthreads();
    for (int off = 1; off < TILE; off <<= 1) {
        int t = (threadIdx.x >= off) ? sh[threadIdx.x - off] : 0;
        __syncthreads();
        sh[threadIdx.x] += t;
        __syncthreads();
    }
    int total = sh[TILE - 1];

    if (threadIdx.x == 0) {
        if (part == 0) {
            s_excl = 0;
            atomicExch(&desc[0], (2ULL << 32) | (unsigned int)total);
        } else {
            atomicExch(&desc[part], (1ULL << 32) | (unsigned int)total);
        }
    }

    if (part > 0 && threadIdx.x < 32) {
        int lane = threadIdx.x;
        int sum = 0;
        int base = part;
        bool done = false;
        while (!done) {
            int idx = base - 32 + lane;
            int flag, val;
            if (idx < 0) { flag = 2; val = 0; }
            else {
                unsigned long long d;
                do {
                    d = *((volatile unsigned long long*)&desc[idx]);
                    flag = (int)(d >> 32);
                } while (flag == 0);
                val = (int)(d & 0xffffffffULL);
            }
            unsigned pmask = __ballot_sync(0xffffffffu, flag == 2);
            int contrib;
            if (pmask) {
                int hi = 31 - __clz(pmask);
                contrib = (lane >= hi) ? val : 0;
                done = true;
            } else {
                contrib = val;
                base -= 32;
            }
#pragma unroll
            for (int off = 16; off >= 1; off >>= 1)
                contrib += __shfl_xor_sync(0xffffffffu, contrib, off);
            sum += contrib;
        }
        if (lane == 0) {
            s_excl = sum;
            atomicExch(&desc[part], (2ULL << 32) | (unsigned int)(sum + total));
        }
    }
    __syncthreads();

    int out = sh[threadIdx.x] + s_excl;
    if (gid < n) rowptr[gid] = out;
    if (gid < n - 1) cursor[gid] = out;   // n = N+1

    // ---- fused layer-1 projection: z[gid] = h[gid] @ W1 (64 -> 10) ----
    if (gid < N) {
        float acc[DIM];
#pragma unroll
        for (int d = 0; d < DIM; d++) acc[d] = 0.0f;
        const float4* hp = reinterpret_cast<const float4*>(h + (size_t)gid * 64);
#pragma unroll
        for (int k4 = 0; k4 < 16; k4++) {
            float4 hv = __ldg(&hp[k4]);
            int k = k4 * 4;
#pragma unroll
            for (int d = 0; d < DIM; d++) {
                acc[d] += hv.x * W1[(k + 0) * DIM + d];
                acc[d] += hv.y * W1[(k + 1) * DIM + d];
                acc[d] += hv.z * W1[(k + 2) * DIM + d];
                acc[d] += hv.w * W1[(k + 3) * DIM + d];
            }
        }
        store_row_h(z, gid, acc);
    }
}

// ---------------- K3: CSR fill (4 edges/thread) ----------------

__global__ void fill_kernel(const int* __restrict__ src, const int* __restrict__ dst,
                            int* __restrict__ cursor, int* __restrict__ srcSorted, int E) {
    int e = (blockIdx.x * blockDim.x + threadIdx.x) * 4;
    if (e + 3 < E) {
        int4 d = __ldg(reinterpret_cast<const int4*>(dst + e));
        int4 s = __ldg(reinterpret_cast<const int4*>(src + e));
        srcSorted[atomicAdd(&cursor[d.x], 1)] = s.x;
        srcSorted[atomicAdd(&cursor[d.y], 1)] = s.y;
        srcSorted[atomicAdd(&cursor[d.z], 1)] = s.z;
        srcSorted[atomicAdd(&cursor[d.w], 1)] = s.w;
    } else {
        for (int k = e; k < E; k++)
            srcSorted[atomicAdd(&cursor[__ldg(&dst[k])], 1)] = __ldg(&src[k]);
    }
}

// ---------------- K4..K8: fused layer ----------------

__global__ void __launch_bounds__(256)
layer_kernel(const __half* __restrict__ z,
             const int* __restrict__ rowptr,
             const int* __restrict__ srcSorted,
             const float* __restrict__ b1,
             const float* __restrict__ W2,
             const float* __restrict__ b2,
             const float* __restrict__ lvec,
             const float* __restrict__ W1n,   // null on last layer
             __half* __restrict__ znext,
             const int* __restrict__ ng,
             float* __restrict__ sAcc, int n) {
    int i = blockIdx.x * blockDim.x + threadIdx.x;
    bool valid = (i < n);

    float r = 0.0f;
    int g = -1;

    if (valid) {
        int beg = rowptr[i];
        int end = rowptr[i + 1];

        float acc[DIM];
#pragma unroll
        for (int d = 0; d < DIM; d++) acc[d] = 0.0f;
        __half2 hacc[5];
        {
            __half2 hz = __floats2half2_rn(0.0f, 0.0f);
#pragma unroll
            for (int j = 0; j < 5; j++) hacc[j] = hz;
        }

        int e = beg;
        // head: align e to 4 (<=3 fp16 adds, then flush)
        while (e < end && (e & 3)) { add_row_h16(z, __ldg(&srcSorted[e]), hacc); e++; }
        flush_h16(acc, hacc);

        // body: aligned int4 groups; flush every 2 groups (<=8 fp16 adds)
        int ngr = (end - e) >> 2;
        for (int q = 0; q < ngr; q++, e += 4) {
            int4 v = __ldg(reinterpret_cast<const int4*>(srcSorted + e));
            add_row_h16(z, v.x, hacc);
            add_row_h16(z, v.y, hacc);
            add_row_h16(z, v.z, hacc);
            add_row_h16(z, v.w, hacc);
            if (q & 1) flush_h16(acc, hacc);
        }
        flush_h16(acc, hacc);

        // tail (<=3 edges)
        for (; e < end; e++) add_row_h16(z, __ldg(&srcSorted[e]), hacc);
        flush_h16(acc, hacc);

        // self term + bias + relu (fp32)
        float u[DIM];
        {
            float self[DIM];
#pragma unroll
            for (int d = 0; d < DIM; d++) self[d] = 0.0f;
            __half2 hs[5];
            __half2 hz = __floats2half2_rn(0.0f, 0.0f);
#pragma unroll
            for (int j = 0; j < 5; j++) hs[j] = hz;
            add_row_h16(z, i, hs);
            flush_h16(self, hs);
#pragma unroll
            for (int d = 0; d < DIM; d++)
                u[d] = fmaxf(self[d] + acc[d] + b1[d], 0.0f);
        }

        float o[DIM];
#pragma unroll
        for (int d = 0; d < DIM; d++) {
            float a2 = b2[d];
#pragma unroll
            for (int k = 0; k < DIM; k++) a2 += u[k] * W2[k * DIM + d];
            o[d] = fmaxf(a2, 0.0f);
        }

#pragma unroll
        for (int d = 0; d < DIM; d++) r += o[d] * lvec[d];
        g = ng[i];

        if (W1n != nullptr) {
            float zn[DIM];
#pragma unroll
            for (int d = 0; d < DIM; d++) {
                float a2 = 0.0f;
#pragma unroll
                for (int k = 0; k < DIM; k++) a2 += o[k] * W1n[k * DIM + d];
                zn[d] = a2;
            }
            store_row_h(znext, i, zn);
        }
    }

    // warp-aggregated readout atomic (ng sorted -> usually uniform per warp)
    unsigned full = 0xffffffffu;
    int g0 = __shfl_sync(full, g, 0);
    bool allsame = __all_sync(full, (g == g0) || !valid);
    if (allsame) {
#pragma unroll
        for (int off = 16; off >= 1; off >>= 1) r += __shfl_xor_sync(full, r, off);
        if ((threadIdx.x & 31) == 0 && g0 >= 0) atomicAdd(&sAcc[g0], r);
    } else {
        if (valid) atomicAdd(&sAcc[g], r);
    }
}

// ---------------- K9: final (sigmoid + re-zero state for next call) --------

__global__ void final_kernel(float* __restrict__ sAcc,
                             const int* __restrict__ ng,
                             float* __restrict__ out,
                             int* __restrict__ rowptr,
                             unsigned long long* __restrict__ desc,
                             int N, int G) {
    int i = blockIdx.x * blockDim.x + threadIdx.x;
    if (i <= N) rowptr[i] = 0;
    if (i < NDESC) desc[i] = 0ULL;
    if (i < G) {
        int lo = 0, hi = N;
        while (lo < hi) { int m = (lo + hi) >> 1; if (__ldg(&ng[m]) < i) lo = m + 1; else hi = m; }
        int a = lo;
        lo = 0; hi = N;
        while (lo < hi) { int m = (lo + hi) >> 1; if (__ldg(&ng[m]) < i + 1) lo = m + 1; else hi = m; }
        float c = (float)(lo - a);
        float v = sAcc[i] / fmaxf(c, 1.0f);
        out[i] = 1.0f / (1.0f + expf(-v));
        sAcc[i] = 0.0f;
    }
}

// ---------------------------------------------------------------------------

extern "C" void kernel_launch(void* const* d_in, const int* in_sizes, int n_in,
                              void* d_out, int out_size) {
    const float* h   = (const float*)d_in[0];
    const int*   src = (const int*)d_in[1];
    const int*   dst = (const int*)d_in[2];
    const int*   ng  = (const int*)d_in[3];

    const float *W1[5], *b1[5], *W2[5], *b2[5], *lv[5];
    for (int i = 0; i < 5; i++) {
        W1[i] = (const float*)d_in[4 + 5 * i + 0];
        b1[i] = (const float*)d_in[4 + 5 * i + 1];
        W2[i] = (const float*)d_in[4 + 5 * i + 2];
        b2[i] = (const float*)d_in[4 + 5 * i + 3];
        lv[i] = (const float*)d_in[4 + 5 * i + 4];
    }

    int N = in_sizes[3];
    int E = in_sizes[1];
    int G = out_size;
    float* out = (float*)d_out;

    __half *zA, *zB;
    float *sAcc;
    int *srcSorted, *rowptr, *cursor;
    unsigned long long* desc;
    cudaGetSymbolAddress((void**)&zA,        g_zA);
    cudaGetSymbolAddress((void**)&zB,        g_zB);
    cudaGetSymbolAddress((void**)&srcSorted, g_srcSorted);
    cudaGetSymbolAddress((void**)&rowptr,    g_rowptr);
    cudaGetSymbolAddress((void**)&cursor,    g_cursor);
    cudaGetSymbolAddress((void**)&desc,      g_desc);
    cudaGetSymbolAddress((void**)&sAcc,      g_s);

    const int BT = 256;
    int nScan = N + 1;
    int nb = (nScan + TILE - 1) / TILE;
    int ebt = (E + 4 * BT - 1) / (4 * BT);

    // 1: histogram (rowptr zero by invariant)
    hist_kernel<<<ebt, BT>>>(dst, rowptr, E);
    // 2: single-pass scan + fused layer-1 projection
    scanproj_kernel<<<nb, TILE>>>(rowptr, nScan, desc, cursor, h, W1[0], zA, N);
    // 3: CSR fill
    fill_kernel<<<ebt, BT>>>(src, dst, cursor, srcSorted, E);

    // 4..8: fused layers (launch #4 = layer1 -> ncu capture target)
    __half* zin = zA;
    __half* zout = zB;
    for (int l = 0; l < 5; l++) {
        layer_kernel<<<(N + BT - 1) / BT, BT>>>(
            zin, rowptr, srcSorted, b1[l], W2[l], b2[l], lv[l],
            (l < 4) ? W1[l + 1] : nullptr, zout, ng, sAcc, N);
        __half* t = zin; zin = zout; zout = t;
    }

    // 9: final sigmoid + re-zero state for the next call
    final_kernel<<<(N + 1 + BT - 1) / BT, BT>>>(sAcc, ng, out, rowptr, desc, N, G);
}

// round 6
// speedup vs baseline: 1.1435x; 1.1435x over previous
#include <cuda_runtime.h>
#include <cuda_fp16.h>
#include <math.h>
#include <stdint.h>

// ---------------------------------------------------------------------------
// NetGIN round 6: pair-cooperative fp16 gather (2 lanes per node, each lane
// loads 16B of the 32B row -> 1 L1tex wavefront per edge instead of 2).
// Launch order: hist(1), scan+proj(2), fill(3), 5x layer(4..8), final(9).
// Invariant: rowptr/desc/sAcc zero on entry (module init + final re-zero).
// hist/fill are scalar (round-4 form; int4 version regressed).
// ---------------------------------------------------------------------------

#define NMAX     500000
#define EMAX     16000000
#define STRIDE_H 16          // halves per row (32 B)
#define DIM      10
#define GMAX     8192
#define TILE     1024
#define NDESC    1024

__device__ __align__(32) __half g_zA[NMAX * STRIDE_H];
__device__ __align__(32) __half g_zB[NMAX * STRIDE_H];
__device__ __align__(16) int g_srcSorted[EMAX];
__device__ int   g_rowptr[NMAX + 1];
__device__ int   g_cursor[NMAX];
__device__ unsigned long long g_desc[NDESC];
__device__ float g_s[GMAX];

// ---------------- fp16 helpers ----------------

__device__ __forceinline__ void store_row_h(__half* __restrict__ z, int i, const float v[DIM]) {
    __half2 p0 = __floats2half2_rn(v[0], v[1]);
    __half2 p1 = __floats2half2_rn(v[2], v[3]);
    __half2 p2 = __floats2half2_rn(v[4], v[5]);
    __half2 p3 = __floats2half2_rn(v[6], v[7]);
    __half2 p4 = __floats2half2_rn(v[8], v[9]);
    uint4 w;
    w.x = *reinterpret_cast<uint32_t*>(&p0);
    w.y = *reinterpret_cast<uint32_t*>(&p1);
    w.z = *reinterpret_cast<uint32_t*>(&p2);
    w.w = *reinterpret_cast<uint32_t*>(&p3);
    __half* zp = z + (size_t)i * STRIDE_H;
    *reinterpret_cast<uint4*>(zp) = w;
    *(reinterpret_cast<uint32_t*>(zp) + 4) = *reinterpret_cast<uint32_t*>(&p4);
}

// one 16B half-row accumulate: 1 LDG.128 + 4 HADD2
__device__ __forceinline__ void add_half_row(const uint4* __restrict__ zb, int s, int half,
                                             __half2 hacc[4]) {
    uint4 v = __ldg(zb + 2 * (size_t)s + half);
    hacc[0] = __hadd2(hacc[0], *reinterpret_cast<__half2*>(&v.x));
    hacc[1] = __hadd2(hacc[1], *reinterpret_cast<__half2*>(&v.y));
    hacc[2] = __hadd2(hacc[2], *reinterpret_cast<__half2*>(&v.z));
    hacc[3] = __hadd2(hacc[3], *reinterpret_cast<__half2*>(&v.w));
}

__device__ __forceinline__ void flush8(float acc[8], __half2 hacc[4]) {
    __half2 hz = __floats2half2_rn(0.0f, 0.0f);
#pragma unroll
    for (int j = 0; j < 4; j++) {
        float2 f = __half22float2(hacc[j]);
        acc[2 * j]     += f.x;
        acc[2 * j + 1] += f.y;
        hacc[j] = hz;
    }
}

// ---------------- K1: histogram of dst (scalar) ----------------

__global__ void hist_kernel(const int* __restrict__ dst, int* __restrict__ rowptr, int E) {
    int e = blockIdx.x * blockDim.x + threadIdx.x;
    if (e < E) atomicAdd(&rowptr[__ldg(&dst[e]) + 1], 1);
}

// ---------------- K2: single-pass lookback scan + layer-1 projection --------

__global__ void __launch_bounds__(TILE)
scanproj_kernel(int* __restrict__ rowptr, int n,
                unsigned long long* __restrict__ desc,
                int* __restrict__ cursor,
                const float* __restrict__ h,
                const float* __restrict__ W1,
                __half* __restrict__ z, int N) {
    __shared__ int sh[TILE];
    __shared__ int s_excl;
    int part = blockIdx.x;
    int gid = part * TILE + threadIdx.x;

    int v = (gid < n) ? rowptr[gid] : 0;
    sh[threadIdx.x] = v;
    __syncthreads();
    for (int off = 1; off < TILE; off <<= 1) {
        int t = (threadIdx.x >= off) ? sh[threadIdx.x - off] : 0;
        __syncthreads();
        sh[threadIdx.x] += t;
        __syncthreads();
    }
    int total = sh[TILE - 1];

    if (threadIdx.x == 0) {
        if (part == 0) {
            s_excl = 0;
            atomicExch(&desc[0], (2ULL << 32) | (unsigned int)total);
        } else {
            atomicExch(&desc[part], (1ULL << 32) | (unsigned int)total);
        }
    }

    if (part > 0 && threadIdx.x < 32) {
        int lane = threadIdx.x;
        int sum = 0;
        int base = part;
        bool done = false;
        while (!done) {
            int idx = base - 32 + lane;
            int flag, val;
            if (idx < 0) { flag = 2; val = 0; }
            else {
                unsigned long long d;
                do {
                    d = *((volatile unsigned long long*)&desc[idx]);
                    flag = (int)(d >> 32);
                } while (flag == 0);
                val = (int)(d & 0xffffffffULL);
            }
            unsigned pmask = __ballot_sync(0xffffffffu, flag == 2);
            int contrib;
            if (pmask) {
                int hi = 31 - __clz(pmask);
                contrib = (lane >= hi) ? val : 0;
                done = true;
            } else {
                contrib = val;
                base -= 32;
            }
#pragma unroll
            for (int off = 16; off >= 1; off >>= 1)
                contrib += __shfl_xor_sync(0xffffffffu, contrib, off);
            sum += contrib;
        }
        if (lane == 0) {
            s_excl = sum;
            atomicExch(&desc[part], (2ULL << 32) | (unsigned int)(sum + total));
        }
    }
    __syncthreads();

    int out = sh[threadIdx.x] + s_excl;
    if (gid < n) rowptr[gid] = out;
    if (gid < n - 1) cursor[gid] = out;   // n = N+1

    // ---- fused layer-1 projection: z[gid] = h[gid] @ W1 (64 -> 10) ----
    if (gid < N) {
        float acc[DIM];
#pragma unroll
        for (int d = 0; d < DIM; d++) acc[d] = 0.0f;
        const float4* hp = reinterpret_cast<const float4*>(h + (size_t)gid * 64);
#pragma unroll
        for (int k4 = 0; k4 < 16; k4++) {
            float4 hv = __ldg(&hp[k4]);
            int k = k4 * 4;
#pragma unroll
            for (int d = 0; d < DIM; d++) {
                acc[d] += hv.x * W1[(k + 0) * DIM + d];
                acc[d] += hv.y * W1[(k + 1) * DIM + d];
                acc[d] += hv.z * W1[(k + 2) * DIM + d];
                acc[d] += hv.w * W1[(k + 3) * DIM + d];
            }
        }
        store_row_h(z, gid, acc);
    }
}

// ---------------- K3: CSR fill (scalar) ----------------

__global__ void fill_kernel(const int* __restrict__ src, const int* __restrict__ dst,
                            int* __restrict__ cursor, int* __restrict__ srcSorted, int E) {
    int e = blockIdx.x * blockDim.x + threadIdx.x;
    if (e < E) {
        int d = __ldg(&dst[e]);
        int p = atomicAdd(&cursor[d], 1);
        srcSorted[p] = __ldg(&src[e]);
    }
}

// ---------------- K4..K8: fused layer (2 lanes per node) ----------------

__global__ void __launch_bounds__(256)
layer_kernel(const __half* __restrict__ z,
             const int* __restrict__ rowptr,
             const int* __restrict__ srcSorted,
             const float* __restrict__ b1,
             const float* __restrict__ W2,
             const float* __restrict__ b2,
             const float* __restrict__ lvec,
             const float* __restrict__ W1n,   // null on last layer
             __half* __restrict__ znext,
             const int* __restrict__ ng,
             float* __restrict__ sAcc, int n) {
    int t = blockIdx.x * blockDim.x + threadIdx.x;
    int i = t >> 1;          // node
    int half = t & 1;        // which 16B half of the row this lane owns
    bool valid = (i < n);

    const uint4* zb = reinterpret_cast<const uint4*>(z);

    float acc[8];
#pragma unroll
    for (int d = 0; d < 8; d++) acc[d] = 0.0f;

    float r = 0.0f;
    int g = -1;

    if (valid) {
        int beg = rowptr[i];
        int end = rowptr[i + 1];

        __half2 hacc[4];
        {
            __half2 hz = __floats2half2_rn(0.0f, 0.0f);
#pragma unroll
            for (int j = 0; j < 4; j++) hacc[j] = hz;
        }

        // self term first
        add_half_row(zb, i, half, hacc);

        // neighbor gather: aligned int4 index groups, predicated ends;
        // flush to fp32 every 2 groups (<= 9 fp16 adds per accumulator).
        int q = 0;
        for (int a = beg & ~3; a < end; a += 4) {
            int4 v = __ldg(reinterpret_cast<const int4*>(srcSorted + a));
            if (a     >= beg)                 add_half_row(zb, v.x, half, hacc);
            if (a + 1 >= beg && a + 1 < end)  add_half_row(zb, v.y, half, hacc);
            if (a + 2 >= beg && a + 2 < end)  add_half_row(zb, v.z, half, hacc);
            if (a + 3 >= beg && a + 3 < end)  add_half_row(zb, v.w, half, hacc);
            if ((++q & 1) == 0) flush8(acc, hacc);
        }
        flush8(acc, hacc);
    }

    // merge pair: even lane (half=0) holds dims 0-7; odd lane holds dims 8-9
    // in acc[0..1]. Bring them over. (all lanes execute the shuffles)
    unsigned full = 0xffffffffu;
    float a8 = __shfl_down_sync(full, acc[0], 1);
    float a9 = __shfl_down_sync(full, acc[1], 1);

    if (valid && half == 0) {
        float u[DIM];
#pragma unroll
        for (int d = 0; d < 8; d++) u[d] = fmaxf(acc[d] + b1[d], 0.0f);
        u[8] = fmaxf(a8 + b1[8], 0.0f);
        u[9] = fmaxf(a9 + b1[9], 0.0f);

        float o[DIM];
#pragma unroll
        for (int d = 0; d < DIM; d++) {
            float a2 = b2[d];
#pragma unroll
            for (int k = 0; k < DIM; k++) a2 += u[k] * W2[k * DIM + d];
            o[d] = fmaxf(a2, 0.0f);
        }

#pragma unroll
        for (int d = 0; d < DIM; d++) r += o[d] * lvec[d];
        g = ng[i];

        if (W1n != nullptr) {
            float zn[DIM];
#pragma unroll
            for (int d = 0; d < DIM; d++) {
                float a2 = 0.0f;
#pragma unroll
                for (int k = 0; k < DIM; k++) a2 += o[k] * W1n[k * DIM + d];
                zn[d] = a2;
            }
            store_row_h(znext, i, zn);
        }
    }

    // warp-aggregated readout atomic. Odd/invalid lanes have g=-1, r=0.
    int g0 = __shfl_sync(full, g, 0);
    bool allsame = __all_sync(full, (g == g0) || (g < 0));
    if (allsame) {
#pragma unroll
        for (int off = 16; off >= 1; off >>= 1) r += __shfl_xor_sync(full, r, off);
        if ((threadIdx.x & 31) == 0 && g0 >= 0) atomicAdd(&sAcc[g0], r);
    } else {
        if (g >= 0) atomicAdd(&sAcc[g], r);
    }
}

// ---------------- K9: final (sigmoid + re-zero state for next call) --------

__global__ void final_kernel(float* __restrict__ sAcc,
                             const int* __restrict__ ng,
                             float* __restrict__ out,
                             int* __restrict__ rowptr,
                             unsigned long long* __restrict__ desc,
                             int N, int G) {
    int i = blockIdx.x * blockDim.x + threadIdx.x;
    if (i <= N) rowptr[i] = 0;
    if (i < NDESC) desc[i] = 0ULL;
    if (i < G) {
        int lo = 0, hi = N;
        while (lo < hi) { int m = (lo + hi) >> 1; if (__ldg(&ng[m]) < i) lo = m + 1; else hi = m; }
        int a = lo;
        lo = 0; hi = N;
        while (lo < hi) { int m = (lo + hi) >> 1; if (__ldg(&ng[m]) < i + 1) lo = m + 1; else hi = m; }
        float c = (float)(lo - a);
        float v = sAcc[i] / fmaxf(c, 1.0f);
        out[i] = 1.0f / (1.0f + expf(-v));
        sAcc[i] = 0.0f;
    }
}

// ---------------------------------------------------------------------------

extern "C" void kernel_launch(void* const* d_in, const int* in_sizes, int n_in,
                              void* d_out, int out_size) {
    const float* h   = (const float*)d_in[0];
    const int*   src = (const int*)d_in[1];
    const int*   dst = (const int*)d_in[2];
    const int*   ng  = (const int*)d_in[3];

    const float *W1[5], *b1[5], *W2[5], *b2[5], *lv[5];
    for (int i = 0; i < 5; i++) {
        W1[i] = (const float*)d_in[4 + 5 * i + 0];
        b1[i] = (const float*)d_in[4 + 5 * i + 1];
        W2[i] = (const float*)d_in[4 + 5 * i + 2];
        b2[i] = (const float*)d_in[4 + 5 * i + 3];
        lv[i] = (const float*)d_in[4 + 5 * i + 4];
    }

    int N = in_sizes[3];
    int E = in_sizes[1];
    int G = out_size;
    float* out = (float*)d_out;

    __half *zA, *zB;
    float *sAcc;
    int *srcSorted, *rowptr, *cursor;
    unsigned long long* desc;
    cudaGetSymbolAddress((void**)&zA,        g_zA);
    cudaGetSymbolAddress((void**)&zB,        g_zB);
    cudaGetSymbolAddress((void**)&srcSorted, g_srcSorted);
    cudaGetSymbolAddress((void**)&rowptr,    g_rowptr);
    cudaGetSymbolAddress((void**)&cursor,    g_cursor);
    cudaGetSymbolAddress((void**)&desc,      g_desc);
    cudaGetSymbolAddress((void**)&sAcc,      g_s);

    const int BT = 256;
    int nScan = N + 1;
    int nb = (nScan + TILE - 1) / TILE;

    // 1: histogram (rowptr zero by invariant)
    hist_kernel<<<(E + BT - 1) / BT, BT>>>(dst, rowptr, E);
    // 2: single-pass scan + fused layer-1 projection
    scanproj_kernel<<<nb, TILE>>>(rowptr, nScan, desc, cursor, h, W1[0], zA, N);
    // 3: CSR fill
    fill_kernel<<<(E + BT - 1) / BT, BT>>>(src, dst, cursor, srcSorted, E);

    // 4..8: fused layers, 2 threads per node (launch #4 = layer1 -> ncu target)
    __half* zin = zA;
    __half* zout = zB;
    for (int l = 0; l < 5; l++) {
        layer_kernel<<<(2 * N + BT - 1) / BT, BT>>>(
            zin, rowptr, srcSorted, b1[l], W2[l], b2[l], lv[l],
            (l < 4) ? W1[l + 1] : nullptr, zout, ng, sAcc, N);
        __half* t = zin; zin = zout; zout = t;
    }

    // 9: final sigmoid + re-zero state for the next call
    final_kernel<<<(N + 1 + BT - 1) / BT, BT>>>(sAcc, ng, out, rowptr, desc, N, G);
}